// round 1
// baseline (speedup 1.0000x reference)
#include <cuda_runtime.h>
#include <cstdint>

// Problem constants (fixed by reference setup_inputs)
#define NB    8        // batch
#define NS    4096     // source points
#define NT    16384    // target points
#define NC    8        // channels
#define NH    10       // neighbors
#define WPB   8        // warps per block
#define FULLM 0xFFFFFFFFu

// Insert (d2, sidx) into sorted-ascending top-NH registers (best[NH-1] is worst).
#define TOPK_INSERT(d2, sidx)                                        \
    if ((d2) < best[NH-1]) {                                         \
        best[NH-1] = (d2); bidx[NH-1] = (sidx);                      \
        _Pragma("unroll")                                            \
        for (int _j = NH-1; _j > 0; --_j) {                          \
            if (best[_j] < best[_j-1]) {                             \
                float _tf = best[_j]; best[_j] = best[_j-1]; best[_j-1] = _tf; \
                int   _ti = bidx[_j]; bidx[_j] = bidx[_j-1]; bidx[_j-1] = _ti; \
            }                                                        \
        }                                                            \
    }

__global__ __launch_bounds__(32 * WPB, 1)
void knn_idw_kernel(const float* __restrict__ x,    // [NB, NS, NC]
                    const float* __restrict__ rel,  // [NT, NS, 2]
                    float* __restrict__ out)        // [NB, NT, NC]
{
    // Per-lane scratch strips (only each lane's own strip is touched -> no sync needed;
    // shared memory is used purely to allow a dynamically-indexed sorted list).
    __shared__ float sh_d[WPB][32 * NH];
    __shared__ int   sh_i[WPB][32 * NH];

    const int warp = threadIdx.x >> 5;
    const int lane = threadIdx.x & 31;
    const int t    = blockIdx.x * WPB + warp;   // target index; grid covers NT exactly

    // -------- Phase 1: stream rel row, per-lane top-NH on squared distance --------
    const float4* relrow = reinterpret_cast<const float4*>(rel + (size_t)t * NS * 2);

    float best[NH];
    int   bidx[NH];
#pragma unroll
    for (int j = 0; j < NH; ++j) { best[j] = 3.4e38f; bidx[j] = 0; }

    // NS/2 = 2048 float4 per row; lane handles 64 of them (128 sources).
#pragma unroll 4
    for (int j = lane; j < NS / 2; j += 32) {
        float4 v = __ldg(&relrow[j]);
        float d0 = v.x * v.x + v.y * v.y;
        float d1 = v.z * v.z + v.w * v.w;
        int s0 = 2 * j;
        TOPK_INSERT(d0, s0);
        TOPK_INSERT(d1, s0 + 1);
    }

    // Dump sorted per-lane list to this lane's shared strip.
    {
        float* dstrip = &sh_d[warp][lane * NH];
        int*   istrip = &sh_i[warp][lane * NH];
#pragma unroll
        for (int j = 0; j < NH; ++j) { dstrip[j] = best[j]; istrip[j] = bidx[j]; }
    }

    // -------- Phase 2: warp merge — NH rounds of warp-wide argmin --------
    float wk[NH];   // unnormalized inverse-distance weights
    int   ik[NH];   // winning source indices
    int p = 0;      // this lane's pointer into its sorted strip
    float wsum = 0.0f;

#pragma unroll
    for (int r = 0; r < NH; ++r) {
        float v  = (p < NH) ? sh_d[warp][lane * NH + p] : 3.4e38f;
        int   vi = (p < NH) ? sh_i[warp][lane * NH + p] : 0;
        int   vl = lane;
        // Butterfly argmin; tie-break on lane so all lanes converge identically.
#pragma unroll
        for (int off = 16; off > 0; off >>= 1) {
            float ov = __shfl_xor_sync(FULLM, v,  off);
            int   oi = __shfl_xor_sync(FULLM, vi, off);
            int   ol = __shfl_xor_sync(FULLM, vl, off);
            if (ov < v || (ov == v && ol < vl)) { v = ov; vi = oi; vl = ol; }
        }
        float dist = sqrtf(v);
        float w = 1.0f / (dist + 1e-10f);
        wk[r] = w;
        ik[r] = vi;
        wsum += w;
        if (lane == vl) ++p;   // winner advances
    }

    const float inv = 1.0f / wsum;

    // -------- Phase 3: gather + weighted sum. 64 outputs, 2 per lane --------
    const int b0 = lane >> 3;       // 0..3
    const int c  = lane & 7;        // 0..7
    float acc0 = 0.0f, acc1 = 0.0f;
#pragma unroll
    for (int k = 0; k < NH; ++k) {
        float w = wk[k] * inv;
        const float* xs = x + (size_t)ik[k] * NC + c;
        acc0 += w * __ldg(xs + (size_t)(b0)     * NS * NC);
        acc1 += w * __ldg(xs + (size_t)(b0 + 4) * NS * NC);
    }
    out[((size_t)(b0)     * NT + t) * NC + c] = acc0;
    out[((size_t)(b0 + 4) * NT + t) * NC + c] = acc1;
}

extern "C" void kernel_launch(void* const* d_in, const int* in_sizes, int n_in,
                              void* d_out, int out_size)
{
    const float* x   = (const float*)d_in[0];   // [8, 4096, 8]
    const float* rel = (const float*)d_in[1];   // [16384, 4096, 2]
    float* out       = (float*)d_out;           // [8, 16384, 8]
    (void)in_sizes; (void)n_in; (void)out_size;

    dim3 grid(NT / WPB);      // 2048 blocks
    dim3 block(32 * WPB);     // 256 threads
    knn_idw_kernel<<<grid, block>>>(x, rel, out);
}

// round 3
// speedup vs baseline: 1.6444x; 1.6444x over previous
#include <cuda_runtime.h>
#include <cstdint>

// Problem constants (fixed by reference setup_inputs)
#define NB    8        // batch
#define NS    4096     // source points
#define NT    16384    // target points
#define NC    8        // channels
#define NH    10       // neighbors
#define WPB   8        // warps per block
#define FULLM 0xFFFFFFFFu

typedef unsigned long long ull;

#define BUFCAP 128     // per-warp candidate buffer (worst case 22 + 64 = 86)
#define TRIG   23      // drain when count >= TRIG (one full sort-32 handles 22)

// Bitonic sort of 32 u64 keys across a warp (ascending; lane k ends with k-th smallest).
__device__ __forceinline__ ull bitonic32(ull key, int lane) {
#pragma unroll
    for (int k = 2; k <= 32; k <<= 1) {
#pragma unroll
        for (int j = k >> 1; j > 0; j >>= 1) {
            ull other = __shfl_xor_sync(FULLM, key, j);
            bool up    = ((lane & k) == 0);
            bool lower = ((lane & j) == 0);
            ull mn = (key < other) ? key : other;
            ull mx = (key < other) ? other : key;
            key = (lower == up) ? mn : mx;
        }
    }
    return key;
}

// Merge buffered candidates into the distributed top-10 (lanes 0..9), refresh thr.
// Uniform across the warp.
__device__ __forceinline__ void drain(ull& top, ull* __restrict__ buf,
                                      int& count, int lane, float& thr) {
    __syncwarp(FULLM);           // order STS pushes before LDS reads
    int cur = 0;
    while (cur < count) {
        int take = count - cur;
        if (take > 22) take = 22;
        ull v;
        if (lane < NH) {
            v = top;
        } else {
            int b = lane - NH;
            v = (b < take) ? buf[cur + b] : ~0ULL;
        }
        v = bitonic32(v, lane);
        if (lane < NH) top = v;
        cur += take;
    }
    count = 0;
    thr = __uint_as_float((unsigned)(__shfl_sync(FULLM, top, NH - 1) >> 32));
}

__global__ __launch_bounds__(32 * WPB, 1)
void knn_idw_kernel(const float* __restrict__ x,    // [NB, NS, NC]
                    const float* __restrict__ rel,  // [NT, NS, 2]
                    float* __restrict__ out)        // [NB, NT, NC]
{
    __shared__ ull sbuf[WPB][BUFCAP];

    const int warp = threadIdx.x >> 5;
    const int lane = threadIdx.x & 31;
    const int t    = blockIdx.x * WPB + warp;     // target index (grid covers NT)
    ull* buf = sbuf[warp];

    const float4* relrow = reinterpret_cast<const float4*>(rel + (size_t)t * NS * 2);
    const unsigned ltmask = (1u << lane) - 1u;

    // Distributed warp top-10: lane k (k<10) holds k-th smallest key.
    // key = (float_bits(d2) << 32) | source_index  -> exact order, ties by lowest idx.
    ull   top   = ~0ULL;
    float thr   = __int_as_float(0x7F800000);     // +inf: first iteration keeps all
    int   count = 0;

    // ---- Stream: 64 iterations/lane, 2 sources per iteration, coalesced 16B loads ----
#pragma unroll 2
    for (int j = lane; j < NS / 2; j += 32) {
        float4 v = __ldg(&relrow[j]);
        float d0 = v.x * v.x + v.y * v.y;
        float d1 = v.z * v.z + v.w * v.w;
        bool c0 = (d0 <= thr);
        bool c1 = (d1 <= thr);
        unsigned m0 = __ballot_sync(FULLM, c0);
        unsigned m1 = __ballot_sync(FULLM, c1);
        if (m0 | m1) {                             // warp-uniform branch
            int n0 = __popc(m0);
            if (c0) buf[count + __popc(m0 & ltmask)] =
                (((ull)__float_as_uint(d0)) << 32) | (unsigned)(2 * j);
            if (c1) buf[count + n0 + __popc(m1 & ltmask)] =
                (((ull)__float_as_uint(d1)) << 32) | (unsigned)(2 * j + 1);
            count += n0 + __popc(m1);
            if (count >= TRIG) drain(top, buf, count, lane, thr);
        }
    }
    if (count > 0) drain(top, buf, count, lane, thr);

    // ---- Weights ----
    float wk[NH];
    int   ik[NH];
    float wsum = 0.0f;
#pragma unroll
    for (int k = 0; k < NH; ++k) {
        ull kk = __shfl_sync(FULLM, top, k);
        float d2 = __uint_as_float((unsigned)(kk >> 32));
        ik[k] = (int)(kk & 0xFFFFFFFFu);
        float w = 1.0f / (sqrtf(d2) + 1e-10f);
        wk[k] = w;
        wsum += w;
    }
    const float inv = 1.0f / wsum;

    // ---- Gather + weighted sum: 64 outputs (8 batch x 8 chan), 2 per lane ----
    const int b0 = lane >> 3;      // 0..3
    const int c  = lane & 7;       // 0..7
    float acc0 = 0.0f, acc1 = 0.0f;
#pragma unroll
    for (int k = 0; k < NH; ++k) {
        float w = wk[k] * inv;
        const float* xs = x + (size_t)ik[k] * NC + c;
        acc0 += w * __ldg(xs + (size_t)(b0)     * NS * NC);
        acc1 += w * __ldg(xs + (size_t)(b0 + 4) * NS * NC);
    }
    out[((size_t)(b0)     * NT + t) * NC + c] = acc0;
    out[((size_t)(b0 + 4) * NT + t) * NC + c] = acc1;
}

extern "C" void kernel_launch(void* const* d_in, const int* in_sizes, int n_in,
                              void* d_out, int out_size)
{
    const float* x   = (const float*)d_in[0];   // [8, 4096, 8]
    const float* rel = (const float*)d_in[1];   // [16384, 4096, 2]
    float* out       = (float*)d_out;           // [8, 16384, 8]
    (void)in_sizes; (void)n_in; (void)out_size;

    dim3 grid(NT / WPB);      // 2048 blocks
    dim3 block(32 * WPB);     // 256 threads
    knn_idw_kernel<<<grid, block>>>(x, rel, out);
}